// round 15
// baseline (speedup 1.0000x reference)
#include <cuda_runtime.h>

#define B_ 32
#define T_ 128
#define N_ 128
#define M_ 64
#define NT_ 192

// ---------------- device scratch (no allocations allowed) ----------------
__device__ float g_V[B_ * N_ * N_];
__device__ float g_v[B_ * N_];
__device__ float g_w[B_ * N_];
__device__ float g_VF[B_ * N_ * NT_];
__device__ float g_Qxx[B_ * N_ * N_];
__device__ float g_Qu[B_ * M_ * NT_];   // rows 0..63: cols 0..127 = Qux, 128..191 = Quu
__device__ float g_qhat[B_ * NT_];
__device__ float g_K[(size_t)T_ * B_ * M_ * N_];
__device__ float g_k[T_ * B_ * M_];

// packed dual-lane fp32 FMA (sm_10x: FFMA2, only reachable via PTX)
__device__ __forceinline__ void ffma2(float2& d, float2 a, float2 b) {
    unsigned long long& dd = reinterpret_cast<unsigned long long&>(d);
    asm("fma.rn.f32x2 %0, %1, %2, %0;"
        : "+l"(dd)
        : "l"(reinterpret_cast<unsigned long long&>(a)),
          "l"(reinterpret_cast<unsigned long long&>(b)));
}

// 8 rows x 4 cols (2 pairs) FFMA2 micro-tile
#define FFMA2_8x2(ar8, bp0, bp1, acc)                                   \
    {                                                                    \
        _Pragma("unroll")                                                \
        for (int _r = 0; _r < 8; _r++) {                                 \
            float2 _aa = make_float2(ar8[_r], ar8[_r]);                  \
            ffma2(acc[_r][0], _aa, bp0);                                 \
            ffma2(acc[_r][1], _aa, bp1);                                 \
        }                                                                \
    }

// ---------------- init ----------------
__global__ void kzero() {
    int idx = blockIdx.x * 256 + threadIdx.x;
    if (idx < B_ * N_ * N_) g_V[idx] = 0.0f;
    if (idx < B_ * N_) g_v[idx] = 0.0f;
}

// ---------------- k1: VF = V @ [A|B]  (uses V symmetry), w = V c + v ----------------
// grid (7, B_), 128 threads. bx 0..5: 64x64 tiles (8x4/thread, f32x2); bx 6: w.
__global__ __launch_bounds__(128) void k1_VF(const float* __restrict__ A,
                                             const float* __restrict__ Bm,
                                             const float* __restrict__ c1, int t) {
    int b = blockIdx.y;
    int bx = blockIdx.x;
    int tid = threadIdx.x;
    const float* Vb = g_V + b * N_ * N_;
    size_t bt = (size_t)b * T_ + t;

    if (bx == 6) {  // w = V c + v  (V symmetric -> coalesced column read)
        __shared__ float cs[128];
        cs[tid] = c1[bt * 128 + tid];
        __syncthreads();
        float acc = g_v[b * 128 + tid];
#pragma unroll 8
        for (int m = 0; m < 128; m++) acc += Vb[m * 128 + tid] * cs[m];
        g_w[b * 128 + tid] = acc;
        return;
    }

    int tr = bx / 3, tc = bx % 3;
    int rb = tr * 64, cb = tc * 64;
    const float* Fsrc; int ldF, coff;
    if (cb < 128) { Fsrc = A + bt * (size_t)(N_ * N_); ldF = 128; coff = cb; }
    else          { Fsrc = Bm + bt * (size_t)(N_ * M_); ldF = 64;  coff = 0;  }

    __shared__ float As[16][64];
    __shared__ float Bs[16][64];
    int tx = tid & 15, ty = tid >> 4;   // tx: cols tx*4..+3 ; ty: rows ty*8..+7
    float2 acc[8][2] = {};
    int mm = tid >> 4, c4 = tid & 15;   // staging coords

    for (int kb = 0; kb < 8; kb++) {
        int k0 = kb * 16;
        // V symmetric: As[kk][r] = V[k0+kk][rb+r]
        *(float4*)&As[mm][c4 * 4]     = *(const float4*)(Vb + (k0 + mm) * 128 + rb + c4 * 4);
        *(float4*)&As[mm + 8][c4 * 4] = *(const float4*)(Vb + (k0 + mm + 8) * 128 + rb + c4 * 4);
        *(float4*)&Bs[mm][c4 * 4]     = *(const float4*)(Fsrc + (size_t)(k0 + mm) * ldF + coff + c4 * 4);
        *(float4*)&Bs[mm + 8][c4 * 4] = *(const float4*)(Fsrc + (size_t)(k0 + mm + 8) * ldF + coff + c4 * 4);
        __syncthreads();
#pragma unroll
        for (int kk = 0; kk < 16; kk++) {
            float4 a0 = *(float4*)&As[kk][ty * 8];
            float4 a1 = *(float4*)&As[kk][ty * 8 + 4];
            float4 b4 = *(float4*)&Bs[kk][tx * 4];
            float2 bp0 = make_float2(b4.x, b4.y), bp1 = make_float2(b4.z, b4.w);
            float ar8[8] = {a0.x, a0.y, a0.z, a0.w, a1.x, a1.y, a1.z, a1.w};
            FFMA2_8x2(ar8, bp0, bp1, acc)
        }
        __syncthreads();
    }
    float* outp = g_VF + b * N_ * NT_;
#pragma unroll
    for (int i = 0; i < 8; i++) {
        *(float4*)(outp + (rb + ty * 8 + i) * NT_ + cb + tx * 4) =
            make_float4(acc[i][0].x, acc[i][0].y, acc[i][1].x, acc[i][1].y);
    }
}

// ---------------- k2: Qxx (3 tiles + mirror) ; [Qux|Quu] = Q_u + B^T VF ; qhat ----------------
// grid (7, B_), 128 threads. bx: 0=(0,0)  1=(1,0)+mirror->(0,1)  2=(1,1)  3,4,5=Qu jb  6=qhat
__global__ __launch_bounds__(128) void k2_Qhat(const float* __restrict__ A,
                                               const float* __restrict__ Bm,
                                               const float* __restrict__ Q,
                                               const float* __restrict__ p, int t) {
    int b = blockIdx.y, bx = blockIdx.x, tid = threadIdx.x;
    size_t bt = (size_t)b * T_ + t;

    if (bx == 6) {  // qhat = p + F^T w
        __shared__ float ws[128];
        ws[tid] = g_w[b * 128 + tid];
        __syncthreads();
        for (int o = tid; o < 192; o += 128) {
            float acc = p[bt * NT_ + o];
            if (o < 128) {
                const float* Ab = A + bt * (size_t)(N_ * N_);
#pragma unroll 4
                for (int n = 0; n < 128; n++) acc += Ab[n * 128 + o] * ws[n];
            } else {
                const float* Bb = Bm + bt * (size_t)(N_ * M_);
                int j = o - 128;
#pragma unroll 4
                for (int n = 0; n < 128; n++) acc += Bb[n * 64 + j] * ws[n];
            }
            g_qhat[b * NT_ + o] = acc;
        }
        return;
    }

    bool isQxx = bx < 3;
    int ib, jb; const float* Asrc; int lda, aoff;
    if (isQxx) {
        ib = (bx == 0) ? 0 : 64;
        jb = (bx == 2) ? 64 : 0;
        Asrc = A + bt * (size_t)(N_ * N_); lda = 128; aoff = ib;
    } else {
        ib = 0; jb = (bx - 3) * 64; Asrc = Bm + bt * (size_t)(N_ * M_); lda = 64; aoff = 0;
    }

    __shared__ float As[16][64];
    __shared__ float Bs[16][64];
    __shared__ float outS[64 * 65];
    int tx = tid & 15, ty = tid >> 4;
    const float* VFb = g_VF + b * N_ * NT_;
    float2 acc[8][2] = {};
    int mm = tid >> 4, c4 = tid & 15;

    for (int kb = 0; kb < 8; kb++) {
        int k0 = kb * 16;
        *(float4*)&As[mm][c4 * 4]     = *(const float4*)(Asrc + (size_t)(k0 + mm) * lda + aoff + c4 * 4);
        *(float4*)&As[mm + 8][c4 * 4] = *(const float4*)(Asrc + (size_t)(k0 + mm + 8) * lda + aoff + c4 * 4);
        *(float4*)&Bs[mm][c4 * 4]     = *(const float4*)(VFb + (k0 + mm) * NT_ + jb + c4 * 4);
        *(float4*)&Bs[mm + 8][c4 * 4] = *(const float4*)(VFb + (k0 + mm + 8) * NT_ + jb + c4 * 4);
        __syncthreads();
#pragma unroll
        for (int kk = 0; kk < 16; kk++) {
            float4 a0 = *(float4*)&As[kk][ty * 8];
            float4 a1 = *(float4*)&As[kk][ty * 8 + 4];
            float4 b4 = *(float4*)&Bs[kk][tx * 4];
            float2 bp0 = make_float2(b4.x, b4.y), bp1 = make_float2(b4.z, b4.w);
            float ar8[8] = {a0.x, a0.y, a0.z, a0.w, a1.x, a1.y, a1.z, a1.w};
            FFMA2_8x2(ar8, bp0, bp1, acc)
        }
        __syncthreads();
    }

    const float* Qb = Q + bt * (size_t)(NT_ * NT_);
    if (isQxx) {
        float* outp = g_Qxx + b * N_ * N_;
#pragma unroll
        for (int i = 0; i < 8; i++) {
            int r = ib + ty * 8 + i, cc = jb + tx * 4;
            float4 q4 = *(const float4*)(Qb + (size_t)r * NT_ + cc);
            float4 o = make_float4(acc[i][0].x + q4.x, acc[i][0].y + q4.y,
                                   acc[i][1].x + q4.z, acc[i][1].y + q4.w);
            *(float4*)(outp + r * N_ + cc) = o;
            if (bx == 1) {  // buffer for mirror
                int rl = ty * 8 + i, cl = tx * 4;
                outS[rl * 65 + cl]     = o.x;
                outS[rl * 65 + cl + 1] = o.y;
                outS[rl * 65 + cl + 2] = o.z;
                outS[rl * 65 + cl + 3] = o.w;
            }
        }
        if (bx == 1) {  // mirror: Qxx[cl][64+rl] = tile[rl][cl]
            __syncthreads();
            for (int idx = tid; idx < 64 * 64; idx += 128) {
                int cl = idx >> 6, rl = idx & 63;
                outp[cl * N_ + 64 + rl] = outS[rl * 65 + cl];
            }
        }
    } else {
        float* outp = g_Qu + b * M_ * NT_;
#pragma unroll
        for (int i = 0; i < 8; i++) {
            int r = ty * 8 + i, cc = jb + tx * 4;
            float4 q4 = *(const float4*)(Qb + (size_t)(128 + r) * NT_ + cc);
            *(float4*)(outp + r * NT_ + cc) =
                make_float4(acc[i][0].x + q4.x, acc[i][0].y + q4.y,
                            acc[i][1].x + q4.z, acc[i][1].y + q4.w);
        }
    }
}

// ---------------- k3: Cholesky with FUSED forward substitution + backward + K/k + Vn + vn ----------------
// grid (4, B_), 512 threads. CTA cg handles Qux columns [cg*32, cg*32+32); cg==0 also qu.
__global__ __launch_bounds__(512) void k3_solve(int t) {
    __shared__ __align__(16) float sL[64 * 68];
    __shared__ __align__(16) float sPT[16 * 68];
    __shared__ __align__(16) float sRb[64 * 36];
    __shared__ float sInvD[64];
    __shared__ float sk[64];
    int b = blockIdx.y, cg = blockIdx.x, tid = threadIdx.x;
    int col0 = cg * 32;
    int ncols = (cg == 0) ? 33 : 32;   // local col 32 = qu (cg 0 only)
    const float* Qub = g_Qu + b * M_ * NT_;

    // stage Quu into sL and the RHS slice into sRb (float4, coalesced)
    for (int idx = tid; idx < 64 * 16; idx += 512) {
        int i = idx >> 4, j4 = idx & 15;
        *(float4*)&sL[i * 68 + j4 * 4] = *(const float4*)(Qub + i * NT_ + 128 + j4 * 4);
    }
    for (int idx = tid; idx < 64 * 8; idx += 512) {
        int i = idx >> 3, c4 = idx & 7;
        *(float4*)&sRb[i * 36 + c4 * 4] = *(const float4*)(Qub + i * NT_ + col0 + c4 * 4);
    }
    if (cg == 0 && tid < 64) sRb[tid * 36 + 32] = g_qhat[b * NT_ + 128 + tid];
    __syncthreads();

    // ---- blocked lower Cholesky with fused forward substitution ----
    for (int kb = 0; kb < 64; kb += 16) {
        // W1: factor 16x16 diagonal block in registers via shfl (warp 0)
        if (tid < 32) {
            int l = tid & 15;
            int row = kb + l;
            float a[16];
#pragma unroll
            for (int i = 0; i < 16; i++) a[i] = sL[row * 68 + kb + i];
#pragma unroll
            for (int i = 0; i < 16; i++) {
                float aii = __shfl_sync(0xffffffffu, a[i], i);
                float dinv = rsqrtf(aii);
                a[i] *= dinv;
                if (tid == i) sInvD[kb + i] = dinv;
#pragma unroll
                for (int c = i + 1; c < 16; c++) {
                    float lci = __shfl_sync(0xffffffffu, a[i], c);
                    a[c] -= a[i] * lci;
                }
            }
            if (tid < 16) {
#pragma unroll
                for (int i = 0; i < 16; i++)
                    if (i <= l) sL[row * 68 + kb + i] = a[i];
            }
        }
        __syncthreads();

        int rem = 48 - kb;
        // W2: chol panel solve (tid < rem)  ||  RHS diag-solve (tid in [64, 64+ncols))
        if (tid < rem) {
            int r = kb + 16 + tid;
            float a[16];
#pragma unroll
            for (int i = 0; i < 16; i++) a[i] = sL[r * 68 + kb + i];
#pragma unroll
            for (int i = 0; i < 16; i++) {
                float s0 = 0.f, s1 = 0.f;
                int m = 0;
#pragma unroll
                for (; m + 1 < i; m += 2) {
                    s0 += a[m] * sL[(kb + i) * 68 + kb + m];
                    s1 += a[m + 1] * sL[(kb + i) * 68 + kb + m + 1];
                }
                if (m < i) s0 += a[m] * sL[(kb + i) * 68 + kb + m];
                a[i] = (a[i] - s0 - s1) * sInvD[kb + i];
            }
#pragma unroll
            for (int i = 0; i < 16; i++) {
                sL[r * 68 + kb + i] = a[i];
                sPT[i * 68 + r] = a[i];
            }
        } else if (tid >= 64 && tid < 64 + ncols) {
            int c = tid - 64;
            float yl[16];
#pragma unroll
            for (int r = 0; r < 16; r++) yl[r] = sRb[(kb + r) * 36 + c];
#pragma unroll
            for (int r = 0; r < 16; r++) {
                float s0 = 0.f, s1 = 0.f;
                int m = 0;
#pragma unroll
                for (; m + 1 < r; m += 2) {
                    s0 += sL[(kb + r) * 68 + kb + m] * yl[m];
                    s1 += sL[(kb + r) * 68 + kb + m + 1] * yl[m + 1];
                }
                if (m < r) s0 += sL[(kb + r) * 68 + kb + m] * yl[m];
                yl[r] = (yl[r] - s0 - s1) * sInvD[kb + r];
                sRb[(kb + r) * 36 + c] = yl[r];
            }
        }
        __syncthreads();

        // W3: chol trailing strips (tid < 384) || RHS bulk elimination (tid >= 384)
        if (rem > 0) {
            if (tid < 384) {
                int nstrip = rem * 16;
                for (int idx = tid; idx < nstrip; idx += 384) {
                    int jr = kb + 16 + (idx >> 4);
                    int c4 = (idx & 15) * 4;
                    if (c4 >= kb + 16 && c4 <= jr) {
                        float4 s = *(float4*)&sL[jr * 68 + c4];
#pragma unroll
                        for (int m = 0; m < 16; m++) {
                            float pj = sPT[m * 68 + jr];
                            float4 pc = *(const float4*)&sPT[m * 68 + c4];
                            s.x -= pj * pc.x; s.y -= pj * pc.y;
                            s.z -= pj * pc.z; s.w -= pj * pc.w;
                        }
                        *(float4*)&sL[jr * 68 + c4] = s;
                    }
                }
            } else {
                int slot = tid - 384;
                int ng = rem >> 4;   // 3, 2, 1
                if (slot < ncols * ng) {
                    int c = slot % ncols;
                    int g = slot / ncols;
                    int r0 = kb + 16 + g * 16;
                    float yv[16];
#pragma unroll
                    for (int m = 0; m < 16; m++) yv[m] = sRb[(kb + m) * 36 + c];
#pragma unroll
                    for (int r = 0; r < 16; r++) {
                        float s = sRb[(r0 + r) * 36 + c];
#pragma unroll
                        for (int m = 0; m < 16; m++)
                            s -= sL[(r0 + r) * 68 + kb + m] * yv[m];
                        sRb[(r0 + r) * 36 + c] = s;
                    }
                }
            }
            __syncthreads();
        }
    }

    // ---- backward substitution: L^T x = y (L read transposed, broadcast) ----
    for (int jb = 3; jb >= 0; jb--) {
        int base = jb * 16;
        if (tid < ncols) {
            int c = tid;
            float yl[16];
#pragma unroll
            for (int r = 0; r < 16; r++) yl[r] = sRb[(base + r) * 36 + c];
#pragma unroll
            for (int r = 15; r >= 0; r--) {
                float s0 = 0.f, s1 = 0.f;
                int m = r + 1;
#pragma unroll
                for (; m + 1 < 16; m += 2) {
                    s0 += sL[(base + m) * 68 + base + r] * yl[m];
                    s1 += sL[(base + m + 1) * 68 + base + r] * yl[m + 1];
                }
                if (m < 16) s0 += sL[(base + m) * 68 + base + r] * yl[m];
                yl[r] = (yl[r] - s0 - s1) * sInvD[base + r];
                sRb[(base + r) * 36 + c] = yl[r];
            }
        }
        __syncthreads();
        if (jb > 0 && tid < ncols * jb) {
            int c = tid % ncols;
            int g = tid / ncols;
            int r0 = g * 16;
            float yv[16];
#pragma unroll
            for (int m = 0; m < 16; m++) yv[m] = sRb[(base + m) * 36 + c];
#pragma unroll
            for (int r = 0; r < 16; r++) {
                float s = sRb[(r0 + r) * 36 + c];
#pragma unroll
                for (int m = 0; m < 16; m++)
                    s -= sL[(base + m) * 68 + (r0 + r)] * yv[m];
                sRb[(r0 + r) * 36 + c] = s;
            }
        }
        __syncthreads();
    }

    // ---- store K slice; cg 0 stores k ----
    {
        float* Kb = g_K + ((size_t)t * B_ + b) * (M_ * N_);
        for (int idx = tid; idx < 64 * 32; idx += 512) {
            int j = idx >> 5, cc = idx & 31;
            Kb[j * 128 + col0 + cc] = -sRb[j * 36 + cc];
        }
        if (cg == 0 && tid < 64) {
            float kv = -sRb[tid * 36 + 32];
            g_k[((size_t)t * B_ + b) * M_ + tid] = kv;
            sk[tid] = kv;
        }
    }
    __syncthreads();

    // ---- vn = qx + Qux^T k (cg 0 only) ----
    if (cg == 0 && tid < 128) {
        float acc = g_qhat[b * NT_ + tid];
#pragma unroll 8
        for (int m = 0; m < 64; m++) acc += Qub[m * NT_ + tid] * sk[m];
        g_v[b * 128 + tid] = acc;
    }

    // ---- Vn slice: Vn[:, col0..col0+31] = Qxx[:, cols] - Qux^T @ y(slice) ----
    {
        int tx = tid & 7;         // col strip: cols col0 + tx*4 .. +3
        int ty = tid >> 3;        // 0..63 -> rows ty*2, ty*2+1
        float acc2[2][4] = {};
#pragma unroll 4
        for (int m = 0; m < 64; m++) {
            float4 yv = *(const float4*)&sRb[m * 36 + tx * 4];
            const float* qrow = Qub + m * NT_ + ty * 2;
            float q0 = qrow[0], q1 = qrow[1];
            acc2[0][0] += q0 * yv.x; acc2[0][1] += q0 * yv.y;
            acc2[0][2] += q0 * yv.z; acc2[0][3] += q0 * yv.w;
            acc2[1][0] += q1 * yv.x; acc2[1][1] += q1 * yv.y;
            acc2[1][2] += q1 * yv.z; acc2[1][3] += q1 * yv.w;
        }
        const float* Qxxb = g_Qxx + b * N_ * N_;
        float* Vb = g_V + b * N_ * N_;
#pragma unroll
        for (int rr = 0; rr < 2; rr++) {
            int i = ty * 2 + rr;
            float4 q4 = *(const float4*)(Qxxb + i * N_ + col0 + tx * 4);
            *(float4*)(Vb + i * N_ + col0 + tx * 4) =
                make_float4(q4.x - acc2[rr][0], q4.y - acc2[rr][1],
                            q4.z - acc2[rr][2], q4.w - acc2[rr][3]);
        }
    }
}

// ---------------- forward rollout ----------------
__global__ __launch_bounds__(256) void kfwd(const float* __restrict__ A,
                                            const float* __restrict__ Bm,
                                            const float* __restrict__ c1,
                                            const float* __restrict__ xinit,
                                            float* __restrict__ out) {
    int b = blockIdx.x, tid = threadIdx.x;
    int warp = tid >> 5, lane = tid & 31;
    __shared__ float sx[128], su[64], sxn[128];
    if (tid < 128) sx[tid] = xinit[b * 128 + tid];
    __syncthreads();

    for (int t = 0; t < 128; t++) {
        size_t bt = (size_t)b * T_ + t;
        const float* Kb = g_K + ((size_t)t * B_ + b) * (M_ * N_);
        const float* kb = g_k + ((size_t)t * B_ + b) * M_;
        for (int r = warp; r < 64; r += 8) {
            const float* kr = Kb + r * 128;
            float s = kr[lane] * sx[lane] + kr[32 + lane] * sx[32 + lane]
                    + kr[64 + lane] * sx[64 + lane] + kr[96 + lane] * sx[96 + lane];
#pragma unroll
            for (int o = 16; o; o >>= 1) s += __shfl_down_sync(0xffffffffu, s, o);
            if (lane == 0) su[r] = s + kb[r];
        }
        if (tid < 128) out[bt * NT_ + tid] = sx[tid];
        __syncthreads();
        if (tid < 64) out[bt * NT_ + 128 + tid] = su[tid];

        const float* Ab = A + bt * (size_t)(N_ * N_);
        const float* Bb = Bm + bt * (size_t)(N_ * M_);
        for (int r = warp; r < 128; r += 8) {
            const float* ar = Ab + r * 128;
            const float* br = Bb + r * 64;
            float s = ar[lane] * sx[lane] + ar[32 + lane] * sx[32 + lane]
                    + ar[64 + lane] * sx[64 + lane] + ar[96 + lane] * sx[96 + lane]
                    + br[lane] * su[lane] + br[32 + lane] * su[32 + lane];
#pragma unroll
            for (int o = 16; o; o >>= 1) s += __shfl_down_sync(0xffffffffu, s, o);
            if (lane == 0) sxn[r] = s + c1[bt * 128 + r];
        }
        __syncthreads();
        if (tid < 128) sx[tid] = sxn[tid];
        __syncthreads();
    }
}

// ---------------- launch ----------------
extern "C" void kernel_launch(void* const* d_in, const int* in_sizes, int n_in,
                              void* d_out, int out_size) {
    const float *A = 0, *Bm = 0, *c1 = 0, *Q = 0, *p = 0, *xinit = 0;
    for (int i = 0; i < n_in; i++) {
        switch (in_sizes[i]) {
            case 67108864:  A = (const float*)d_in[i]; break;      // 32*128*128*128
            case 33554432:  Bm = (const float*)d_in[i]; break;     // 32*128*128*64
            case 524288:    c1 = (const float*)d_in[i]; break;     // 32*128*128
            case 150994944: Q = (const float*)d_in[i]; break;      // 32*128*192*192
            case 786432:    p = (const float*)d_in[i]; break;      // 32*128*192
            case 4096:      xinit = (const float*)d_in[i]; break;  // 32*128
        }
    }
    float* out = (float*)d_out;

    kzero<<<(B_ * N_ * N_ + 255) / 256, 256>>>();
    for (int t = T_ - 1; t >= 0; t--) {
        k1_VF<<<dim3(7, B_), 128>>>(A, Bm, c1, t);
        k2_Qhat<<<dim3(7, B_), 128>>>(A, Bm, Q, p, t);
        k3_solve<<<dim3(4, B_), 512>>>(t);
    }
    kfwd<<<B_, 256>>>(A, Bm, c1, xinit, out);
}